// round 2
// baseline (speedup 1.0000x reference)
#include <cuda_runtime.h>

// ROIAlign: features (B=4, C=64, H=38, W=38) fp32, rois (B, 2904, 4) fp32
// -> out (11616, 64, 7, 7) fp32.
//
// R2: L1tex was the bottleneck (80%) due to scattered per-pixel gathers in
// NCHW. Fix: transpose features to NHWC scratch (1.48 MB, __device__ global),
// so the 4 bilinear corners become coalesced 256B channel runs (float4 x 16
// threads). Output staged through smem (smem linear index == output linear
// index) and flushed as coalesced float4 stores.

#define FB 4
#define FH 38
#define FW 38
#define FC 64
#define OS 7
#define PLANE (FH * FW)          // 1444
#define PER_ROI (FC * OS * OS)   // 3136

__device__ float g_nhwc[FB * PLANE * FC];   // [b][h][w][c], 1.48 MB

// ---------------- kernel 1: NCHW -> NHWC tiled transpose ----------------
// Per batch: transpose [64][1444] -> [1444][64]. 32x32 tiles via smem.
__global__ __launch_bounds__(256)
void nchw2nhwc_kernel(const float* __restrict__ feat)
{
    __shared__ float tile[32][33];
    const int b = blockIdx.z;
    const int hw0 = blockIdx.x * 32;       // hw tile base
    const int c0 = blockIdx.y * 32;        // channel tile base (0 or 32)

    const float* in = feat + (size_t)b * FC * PLANE;
    float* outp = g_nhwc + (size_t)b * PLANE * FC;

    const int tx = threadIdx.x;            // 0..31
    const int ty = threadIdx.y;            // 0..7

#pragma unroll
    for (int i = 0; i < 32; i += 8) {
        const int c = c0 + ty + i;
        const int hw = hw0 + tx;
        if (hw < PLANE)
            tile[ty + i][tx] = in[c * PLANE + hw];
    }
    __syncthreads();
#pragma unroll
    for (int i = 0; i < 32; i += 8) {
        const int hw = hw0 + ty + i;
        const int c = c0 + tx;
        if (hw < PLANE)
            outp[hw * FC + c] = tile[tx][ty + i];
    }
}

// ---------------- kernel 2: ROIAlign from NHWC ----------------
// One block per ROI. blockDim = (16, 49):
//   threadIdx.y = p in [0,49): output pixel; weights/indices in registers.
//   threadIdx.x = cg in [0,16): channel group, handles channels 4cg..4cg+3
//                 via float4 -> coalesced 256B gathers per corner.
// Results staged in smem at [c*49+p] == output linear index, then flushed
// as 784 coalesced float4 stores.
__global__ __launch_bounds__(784, 2)
void roialign_nhwc_kernel(const float* __restrict__ rois,
                          float* __restrict__ out,
                          int nb_per_batch)
{
    __shared__ float s[PER_ROI];           // 12544 B

    const int n = blockIdx.x;              // roi index
    const int p = threadIdx.y;             // 0..48
    const int cg = threadIdx.x;            // 0..15
    const int b = n / nb_per_batch;

    const float4 r = __ldg(reinterpret_cast<const float4*>(rois) + n);
    const float rw = fmaxf(r.z - r.x, 1.0f);
    const float rh = fmaxf(r.w - r.y, 1.0f);

    const int ox = p % OS;
    const int oy = p / OS;

    const float x = fmaf((float)ox * (1.0f / 6.0f), rw, r.x);
    const float y = fmaf((float)oy * (1.0f / 6.0f), rh, r.y);

    const float x0f = floorf(x);
    const float y0f = floorf(y);
    const float fx = x - x0f;
    const float fy = y - y0f;

    const int x0 = (int)x0f, y0 = (int)y0f;
    const int x1 = x0 + 1, y1 = y0 + 1;

    const bool vx0 = (x0 >= 0) && (x0 <= FW - 1);
    const bool vx1 = (x1 >= 0) && (x1 <= FW - 1);
    const bool vy0 = (y0 >= 0) && (y0 <= FH - 1);
    const bool vy1 = (y1 >= 0) && (y1 <= FH - 1);

    const int xi0 = min(max(x0, 0), FW - 1);
    const int xi1 = min(max(x1, 0), FW - 1);
    const int yi0 = min(max(y0, 0), FH - 1);
    const int yi1 = min(max(y1, 0), FH - 1);

    const float wx0 = 1.0f - fx, wx1 = fx;
    const float wy0 = 1.0f - fy, wy1 = fy;

    const float w00 = (vx0 && vy0) ? wx0 * wy0 : 0.0f;
    const float w01 = (vx1 && vy0) ? wx1 * wy0 : 0.0f;
    const float w10 = (vx0 && vy1) ? wx0 * wy1 : 0.0f;
    const float w11 = (vx1 && vy1) ? wx1 * wy1 : 0.0f;

    const float* __restrict__ fb = g_nhwc + (size_t)b * PLANE * FC + 4 * cg;
    const float4 v00 = *reinterpret_cast<const float4*>(fb + (yi0 * FW + xi0) * FC);
    const float4 v01 = *reinterpret_cast<const float4*>(fb + (yi0 * FW + xi1) * FC);
    const float4 v10 = *reinterpret_cast<const float4*>(fb + (yi1 * FW + xi0) * FC);
    const float4 v11 = *reinterpret_cast<const float4*>(fb + (yi1 * FW + xi1) * FC);

    float4 a;
    a.x = fmaf(w00, v00.x, fmaf(w01, v01.x, fmaf(w10, v10.x, w11 * v11.x)));
    a.y = fmaf(w00, v00.y, fmaf(w01, v01.y, fmaf(w10, v10.y, w11 * v11.y)));
    a.z = fmaf(w00, v00.z, fmaf(w01, v01.z, fmaf(w10, v10.z, w11 * v11.z)));
    a.w = fmaf(w00, v00.w, fmaf(w01, v01.w, fmaf(w10, v10.w, w11 * v11.w)));

    const int c = 4 * cg;
    s[(c + 0) * (OS * OS) + p] = a.x;
    s[(c + 1) * (OS * OS) + p] = a.y;
    s[(c + 2) * (OS * OS) + p] = a.z;
    s[(c + 3) * (OS * OS) + p] = a.w;

    __syncthreads();

    const int tid = threadIdx.y * 16 + threadIdx.x;   // 0..783
    float4* o4 = reinterpret_cast<float4*>(out + (size_t)n * PER_ROI);
    o4[tid] = *reinterpret_cast<const float4*>(&s[4 * tid]);
}

extern "C" void kernel_launch(void* const* d_in, const int* in_sizes, int n_in,
                              void* d_out, int out_size)
{
    const float* feat = (const float*)d_in[0];   // (B, 64, 38, 38)
    const float* rois = (const float*)d_in[1];   // (B, Nb, 4)
    float* out = (float*)d_out;

    const int B = in_sizes[0] / (FC * PLANE);    // 4
    const int n_roi = in_sizes[1] / 4;           // 11616
    const int nb = n_roi / B;                    // 2904

    dim3 tgrid((PLANE + 31) / 32, FC / 32, B);   // (46, 2, 4)
    dim3 tblock(32, 8);
    nchw2nhwc_kernel<<<tgrid, tblock>>>(feat);

    dim3 block(16, 49);
    roialign_nhwc_kernel<<<n_roi, block>>>(rois, out, nb);
}

// round 3
// speedup vs baseline: 1.0694x; 1.0694x over previous
#include <cuda_runtime.h>

// ROIAlign: features (4, 64, 38, 38) fp32, rois (4, 2904, 4) -> (11616, 64, 7, 7).
//
// R3: NHWC gathers (coalesced 128B channel runs), but:
//  - bilinear weights computed ONCE per pixel (49 threads) -> smem broadcast
//  - each ROI split across 2 blocks of 392 threads (32 channels each) for
//    high occupancy
//  - bank-conflict-free smem staging, coalesced float4 output flush

#define FB 4
#define FH 38
#define FW 38
#define FC 64
#define OS 7
#define PLANE (FH * FW)          // 1444
#define PER_ROI (FC * OS * OS)   // 3136
#define HALF_CH 32
#define HALF_OUT (HALF_CH * OS * OS)  // 1568

__device__ float g_nhwc[FB * PLANE * FC];   // [b][h][w][c], 1.48 MB

// ---------------- kernel 1: NCHW -> NHWC tiled transpose ----------------
__global__ __launch_bounds__(256)
void nchw2nhwc_kernel(const float* __restrict__ feat)
{
    __shared__ float tile[32][33];
    const int b = blockIdx.z;
    const int hw0 = blockIdx.x * 32;
    const int c0 = blockIdx.y * 32;

    const float* in = feat + (size_t)b * FC * PLANE;
    float* outp = g_nhwc + (size_t)b * PLANE * FC;

    const int tx = threadIdx.x;
    const int ty = threadIdx.y;

#pragma unroll
    for (int i = 0; i < 32; i += 8) {
        const int c = c0 + ty + i;
        const int hw = hw0 + tx;
        if (hw < PLANE)
            tile[ty + i][tx] = in[c * PLANE + hw];
    }
    __syncthreads();
#pragma unroll
    for (int i = 0; i < 32; i += 8) {
        const int hw = hw0 + ty + i;
        const int c = c0 + tx;
        if (hw < PLANE)
            outp[hw * FC + c] = tile[tx][ty + i];
    }
}

// ---------------- kernel 2: ROIAlign from NHWC ----------------
// grid = (n_roi, 2). blockDim = (8, 49) = 392 threads.
//   blockIdx.y = half: channels [32*half, 32*half+32)
//   threadIdx.x = cg in [0,8): 4 channels (float4) at 32*half + 4*cg
//   threadIdx.y = p in [0,49): output pixel
__global__ __launch_bounds__(392, 5)
void roialign_nhwc_kernel(const float* __restrict__ rois,
                          float* __restrict__ out,
                          int nb_per_batch)
{
    __shared__ float4 sw[OS * OS];       // bilinear weights per pixel
    __shared__ int4   so[OS * OS];       // corner pixel offsets per pixel
    __shared__ float  s[HALF_OUT];       // staging: [c_local*49 + p]

    const int n = blockIdx.x;
    const int half = blockIdx.y;
    const int cg = threadIdx.x;          // 0..7
    const int p = threadIdx.y;           // 0..48
    const int tid = cg + 8 * p;          // 0..391
    const int b = n / nb_per_batch;

    // ---- phase 1: weights/offsets, one thread per pixel ----
    if (tid < OS * OS) {
        const float4 r = __ldg(reinterpret_cast<const float4*>(rois) + n);
        const float rw = fmaxf(r.z - r.x, 1.0f);
        const float rh = fmaxf(r.w - r.y, 1.0f);

        const int q = tid;
        const int ox = q % OS;
        const int oy = q / OS;

        const float x = fmaf((float)ox * (1.0f / 6.0f), rw, r.x);
        const float y = fmaf((float)oy * (1.0f / 6.0f), rh, r.y);

        const float x0f = floorf(x);
        const float y0f = floorf(y);
        const float fx = x - x0f;
        const float fy = y - y0f;

        const int x0 = (int)x0f, y0 = (int)y0f;
        const int x1 = x0 + 1, y1 = y0 + 1;

        const bool vx0 = (x0 >= 0) && (x0 <= FW - 1);
        const bool vx1 = (x1 >= 0) && (x1 <= FW - 1);
        const bool vy0 = (y0 >= 0) && (y0 <= FH - 1);
        const bool vy1 = (y1 >= 0) && (y1 <= FH - 1);

        const int xi0 = min(max(x0, 0), FW - 1);
        const int xi1 = min(max(x1, 0), FW - 1);
        const int yi0 = min(max(y0, 0), FH - 1);
        const int yi1 = min(max(y1, 0), FH - 1);

        const float wx0 = 1.0f - fx, wx1 = fx;
        const float wy0 = 1.0f - fy, wy1 = fy;

        float4 w;
        w.x = (vx0 && vy0) ? wx0 * wy0 : 0.0f;
        w.y = (vx1 && vy0) ? wx1 * wy0 : 0.0f;
        w.z = (vx0 && vy1) ? wx0 * wy1 : 0.0f;
        w.w = (vx1 && vy1) ? wx1 * wy1 : 0.0f;
        sw[q] = w;

        int4 o;
        o.x = (yi0 * FW + xi0) * FC;
        o.y = (yi0 * FW + xi1) * FC;
        o.z = (yi1 * FW + xi0) * FC;
        o.w = (yi1 * FW + xi1) * FC;
        so[q] = o;
    }
    __syncthreads();

    // ---- phase 2: gather + blend ----
    const float4 w = sw[p];
    const int4 o = so[p];

    const float* __restrict__ fb =
        g_nhwc + (size_t)b * PLANE * FC + HALF_CH * half + 4 * cg;

    const float4 v00 = *reinterpret_cast<const float4*>(fb + o.x);
    const float4 v01 = *reinterpret_cast<const float4*>(fb + o.y);
    const float4 v10 = *reinterpret_cast<const float4*>(fb + o.z);
    const float4 v11 = *reinterpret_cast<const float4*>(fb + o.w);

    float4 a;
    a.x = fmaf(w.x, v00.x, fmaf(w.y, v01.x, fmaf(w.z, v10.x, w.w * v11.x)));
    a.y = fmaf(w.x, v00.y, fmaf(w.y, v01.y, fmaf(w.z, v10.y, w.w * v11.y)));
    a.z = fmaf(w.x, v00.z, fmaf(w.y, v01.z, fmaf(w.z, v10.z, w.w * v11.z)));
    a.w = fmaf(w.x, v00.w, fmaf(w.y, v01.w, fmaf(w.z, v10.w, w.w * v11.w)));

    // staging: conflict-free scalar STS (banks (4cg+17j+p) all distinct/warp)
    const int cl = 4 * cg;               // local channel 0..31
    s[(cl + 0) * (OS * OS) + p] = a.x;
    s[(cl + 1) * (OS * OS) + p] = a.y;
    s[(cl + 2) * (OS * OS) + p] = a.z;
    s[(cl + 3) * (OS * OS) + p] = a.w;

    __syncthreads();

    // ---- flush: 392 coalesced float4 stores ----
    float4* o4 = reinterpret_cast<float4*>(out + (size_t)n * PER_ROI + half * HALF_OUT);
    o4[tid] = reinterpret_cast<const float4*>(s)[tid];
}

extern "C" void kernel_launch(void* const* d_in, const int* in_sizes, int n_in,
                              void* d_out, int out_size)
{
    const float* feat = (const float*)d_in[0];   // (B, 64, 38, 38)
    const float* rois = (const float*)d_in[1];   // (B, Nb, 4)
    float* out = (float*)d_out;

    const int B = in_sizes[0] / (FC * PLANE);    // 4
    const int n_roi = in_sizes[1] / 4;           // 11616
    const int nb = n_roi / B;                    // 2904

    dim3 tgrid((PLANE + 31) / 32, FC / 32, B);
    dim3 tblock(32, 8);
    nchw2nhwc_kernel<<<tgrid, tblock>>>(feat);

    dim3 grid(n_roi, 2);
    dim3 block(8, 49);
    roialign_nhwc_kernel<<<grid, block>>>(rois, out, nb);
}